// round 11
// baseline (speedup 1.0000x reference)
#include <cuda_runtime.h>
#include <cuda_fp16.h>
#include <math.h>
#include <stdint.h>

#define B_ 32
#define T_ 2048
#define D_ 1024
#define U_ 1024

// ---------------- device scratch (no allocation allowed) ----------------
__device__ float   g_cu[B_ * U_];         // query @ W2 + b2 + b1
__device__ float   g_qpart[8 * B_ * U_];  // qproj split-K partials
__device__ float   g_logits[B_ * T_];     // pre-softmax scores
__device__ __half  g_w1t[U_ * D_];        // W1^T in fp16  [U, D]
__device__ float   g_cpart[16 * B_ * D_]; // context partials

// ---------------- helpers ----------------
__device__ __forceinline__ uint32_t smem_u32(const void* p) {
    uint32_t a;
    asm("{ .reg .u64 t; cvta.to.shared.u64 t, %1; cvt.u32.u64 %0, t; }" : "=r"(a) : "l"(p));
    return a;
}
__device__ __forceinline__ uint32_t pack_f16x2(float lo, float hi) {
    uint32_t r;
    asm("cvt.rn.f16x2.f32 %0, %1, %2;" : "=r"(r) : "f"(hi), "f"(lo));
    return r;
}
__device__ __forceinline__ void ldsm_x4(uint32_t& r0, uint32_t& r1, uint32_t& r2, uint32_t& r3,
                                        uint32_t addr) {
    asm volatile("ldmatrix.sync.aligned.m8n8.x4.shared.b16 {%0,%1,%2,%3}, [%4];"
                 : "=r"(r0), "=r"(r1), "=r"(r2), "=r"(r3) : "r"(addr));
}
__device__ __forceinline__ void mma16816(float* c, const uint32_t* a, uint32_t b0, uint32_t b1) {
    asm volatile(
        "mma.sync.aligned.m16n8k16.row.col.f32.f16.f16.f32 "
        "{%0,%1,%2,%3},{%4,%5,%6,%7},{%8,%9},{%0,%1,%2,%3};"
        : "+f"(c[0]), "+f"(c[1]), "+f"(c[2]), "+f"(c[3])
        : "r"(a[0]), "r"(a[1]), "r"(a[2]), "r"(a[3]), "r"(b0), "r"(b1));
}
__device__ __forceinline__ void cp_async16(uint32_t sdst, const void* gsrc) {
    asm volatile("cp.async.cg.shared.global [%0], [%1], 16;" :: "r"(sdst), "l"(gsrc));
}
__device__ __forceinline__ void cp_commit() {
    asm volatile("cp.async.commit_group;" ::: "memory");
}
__device__ __forceinline__ void cp_wait1() {
    asm volatile("cp.async.wait_group 1;" ::: "memory");
}

// ---------------------------------------------------------------------------
// W1 [D,U] fp32 -> g_w1t [U,D] fp16 (transpose + convert)
// ---------------------------------------------------------------------------
__global__ void w1t_kernel(const float* __restrict__ W1)
{
    __shared__ float tile[32][33];
    const int u0 = blockIdx.x * 32, d0 = blockIdx.y * 32;
    const int tx = threadIdx.x, ty = threadIdx.y;
#pragma unroll
    for (int i = 0; i < 32; i += 8)
        tile[ty + i][tx] = W1[(size_t)(d0 + ty + i) * U_ + u0 + tx];
    __syncthreads();
#pragma unroll
    for (int i = 0; i < 32; i += 8)
        g_w1t[(size_t)(u0 + ty + i) * D_ + d0 + tx] = __float2half_rn(tile[tx][ty + i]);
}

// ---------------------------------------------------------------------------
// q_proj split-K: partial dot over 128 d's per block
// ---------------------------------------------------------------------------
__global__ void qproj_part_kernel(const float* __restrict__ query,
                                  const float* __restrict__ W2)
{
    __shared__ float qs[128];
    const int b = blockIdx.y;
    const int c = blockIdx.z;
    const int u = blockIdx.x * 256 + threadIdx.x;
    const int d0 = c * 128;

    if (threadIdx.x < 128)
        qs[threadIdx.x] = query[b * D_ + d0 + threadIdx.x];
    __syncthreads();

    float acc = 0.0f;
#pragma unroll 8
    for (int i = 0; i < 128; ++i)
        acc = fmaf(qs[i], W2[(size_t)(d0 + i) * U_ + u], acc);
    g_qpart[(c * B_ + b) * U_ + u] = acc;
}

__global__ void qproj_reduce_kernel(const float* __restrict__ b1,
                                    const float* __restrict__ b2)
{
    const int i = blockIdx.x * 256 + threadIdx.x;   // over B*U
    const int u = i & (U_ - 1);
    float s = b1[u] + b2[u];
#pragma unroll
    for (int c = 0; c < 8; ++c)
        s += g_qpart[c * (B_ * U_) + i];
    g_cu[i] = s;
}

// ---------------------------------------------------------------------------
// Fused score GEMM (mma.sync fp16), 128 threads, warp tile 64m x 64n:
//   logits[b,t] = V . tanh(values[b,t,:] @ W1 + qproj_cu[b,:]) + bv
// 4 warps; each warp owns all 64 m-rows and a 64-col n-quarter.
// 8 ldsm per 32 mma (0.25/mma). A resident in smem; B in a 3-stage
// cp.async ring (64 chunks of 256u x 64k), 1 sync per chunk.
// Swizzle term is mt/nt-invariant (rowA&7 == lane&7), so ldsm addresses
// are 4+4 registers plus immediate offsets.
// ---------------------------------------------------------------------------
#define NCHUNK 64                      // 4 passes x 16 chunks
#define SMA    0                       // 64 x 2048B = 131072
#define SMB    131072                  // 3 stages x 32768
#define SMRED  (SMB + 3 * 32768)       // 64 x 4 f32
#define SMTOT  (SMRED + 1024)          // 230400 bytes

__global__ void __launch_bounds__(128, 1)
score_kernel(const float* __restrict__ values,
             const float* __restrict__ V,
             const float* __restrict__ bv)
{
    extern __shared__ char smem[];
    const uint32_t sb = smem_u32(smem);
    const int tid  = threadIdx.x;
    const int lane = tid & 31;
    const int warp = tid >> 5;           // n-quarter owner
    const int g8 = lane >> 2;
    const int t4 = lane & 3;
    const int e  = lane >> 4;            // 0/1: which 8-col group of ldsm

    const int b  = blockIdx.x >> 5;          // 32 t-tiles per batch
    const int t0 = (blockIdx.x & 31) * 64;

    float* sred = (float*)(smem + SMRED);

    // --- cp.async bases: per-thread constant parts ---
    const int r0 = tid >> 3, cs = tid & 7;        // B slot row0 (0..15), 16B col
    const uint32_t sdst0 = sb + SMB + r0 * 128 + ((cs ^ (r0 & 7)) << 4);
    const char* gbase = ((const char*)g_w1t) + r0 * 2048 + cs * 16;

    // chunk issue: 256u x 64k fp16 into stage gc%3 (16 cp per thread)
    auto issue_chunk = [&](int gc) {
        if (gc < NCHUNK) {
            const uint32_t s0 = sdst0 + (uint32_t)(gc % 3) * 32768;
            const char* gs = gbase + (size_t)(gc >> 4) * 524288 + (gc & 15) * 128;
#pragma unroll
            for (int j = 0; j < 16; ++j)
                cp_async16(s0 + j * 2048, gs + (size_t)j * 32768);
        }
        cp_commit();
    };

    // prologue FIRST: 2 chunks in flight while we load/convert A
    issue_chunk(0);
    issue_chunk(1);

    // ---- A resident: 64 rows x 1024 k, fp32 -> fp16, xor-swizzled ----
    // iteration it = row; thread tid = 16B col slot (0..127)
    const float* vbase = values + ((size_t)b * T_ + t0) * D_;
    {
        const uint32_t arow_sw = ((uint32_t)tid << 4);   // c<<4; xor applied below
        for (int row = 0; row < 64; ++row) {
            const float* src = vbase + (size_t)row * D_ + tid * 8;
            float4 f0 = *(const float4*)(src);
            float4 f1 = *(const float4*)(src + 4);
            uint4 o;
            o.x = pack_f16x2(f0.x, f0.y);
            o.y = pack_f16x2(f0.z, f0.w);
            o.z = pack_f16x2(f1.x, f1.y);
            o.w = pack_f16x2(f1.z, f1.w);
            *(uint4*)(smem + SMA + row * 2048 + (arow_sw ^ ((row & 7) << 4))) = o;
        }
    }

    // ---- ldsm address bases (swizzle term mt/nt-invariant) ----
    const int l15 = lane & 15, swl = lane & 7;
    uint32_t a_adr[4], b_adr[4];
#pragma unroll
    for (int ks = 0; ks < 4; ++ks) {
        const uint32_t sw = (uint32_t)(((2 * ks + e) ^ swl) << 4);
        a_adr[ks] = sb + SMA + l15 * 2048 + sw;                      // + mt*32768 + c*128
        b_adr[ks] = sb + SMB + (warp * 64 + l15) * 128 + sw;         // + nt*2048 + soff
    }

    float spart[4][2];
#pragma unroll
    for (int mt = 0; mt < 4; ++mt) { spart[mt][0] = 0.f; spart[mt][1] = 0.f; }

    int g = 0;

    for (int pass = 0; pass < 4; ++pass) {
        const int u0 = pass * 256;

        float acc[4][8][4];
#pragma unroll
        for (int mt = 0; mt < 4; ++mt)
#pragma unroll
            for (int j = 0; j < 8; ++j)
#pragma unroll
                for (int r = 0; r < 4; ++r) acc[mt][j][r] = 0.f;

        uint32_t a_c[4];
#pragma unroll
        for (int ks = 0; ks < 4; ++ks) a_c[ks] = a_adr[ks];

        for (int c = 0; c < 16; ++c, ++g) {
            cp_wait1();
            __syncthreads();
            issue_chunk(g + 2);

            const uint32_t soff = (uint32_t)(g % 3) * 32768;

#pragma unroll
            for (int ks = 0; ks < 4; ++ks) {
                uint32_t af[4][4], bf[4][4];
#pragma unroll
                for (int mt = 0; mt < 4; ++mt)
                    ldsm_x4(af[mt][0], af[mt][1], af[mt][2], af[mt][3],
                            a_c[ks] + mt * 32768);
#pragma unroll
                for (int nt = 0; nt < 4; ++nt)
                    ldsm_x4(bf[nt][0], bf[nt][1], bf[nt][2], bf[nt][3],
                            b_adr[ks] + soff + nt * 2048);
#pragma unroll
                for (int nt = 0; nt < 4; ++nt)
#pragma unroll
                    for (int mt = 0; mt < 4; ++mt) {
                        mma16816(acc[mt][nt * 2 + 0], af[mt], bf[nt][0], bf[nt][2]);
                        mma16816(acc[mt][nt * 2 + 1], af[mt], bf[nt][1], bf[nt][3]);
                    }
            }
#pragma unroll
            for (int ks = 0; ks < 4; ++ks) a_c[ks] += 128;
        }

        // ---- epilogue: tanh + dot V folded into per-row partials ----
        float cuv[16], vvv[16];
#pragma unroll
        for (int j = 0; j < 8; ++j)
#pragma unroll
            for (int ee = 0; ee < 2; ++ee) {
                int u = u0 + warp * 64 + j * 8 + t4 * 2 + ee;
                cuv[j * 2 + ee] = g_cu[b * U_ + u];
                vvv[j * 2 + ee] = V[u];
            }
#pragma unroll
        for (int mt = 0; mt < 4; ++mt)
#pragma unroll
            for (int j = 0; j < 8; ++j)
#pragma unroll
                for (int r = 0; r < 4; ++r) {
                    float x = acc[mt][j][r] + cuv[j * 2 + (r & 1)];
                    spart[mt][r >> 1] =
                        fmaf(tanhf(x), vvv[j * 2 + (r & 1)], spart[mt][r >> 1]);
                }
    }

    // reduce across quad lanes (cols), stash per-warp partials
#pragma unroll
    for (int mt = 0; mt < 4; ++mt)
#pragma unroll
        for (int h = 0; h < 2; ++h) {
            float v = spart[mt][h];
            v += __shfl_xor_sync(0xffffffffu, v, 1);
            v += __shfl_xor_sync(0xffffffffu, v, 2);
            if (t4 == 0) {
                int row = mt * 16 + h * 8 + g8;
                sred[row * 4 + warp] = v;
            }
        }
    __syncthreads();
    if (tid < 64) {
        const float* rp = &sred[tid * 4];
        g_logits[b * T_ + t0 + tid] = (rp[0] + rp[1]) + (rp[2] + rp[3]) + bv[0];
    }
}

// ---------------------------------------------------------------------------
// softmax over T per batch
// ---------------------------------------------------------------------------
__global__ void softmax_kernel(float* __restrict__ weights)
{
    __shared__ float red[256];
    const int b = blockIdx.x;
    const int tid = threadIdx.x;

    float m = -INFINITY;
    for (int t = tid; t < T_; t += 256)
        m = fmaxf(m, g_logits[b * T_ + t]);
    red[tid] = m;
    __syncthreads();
    for (int s = 128; s > 0; s >>= 1) {
        if (tid < s) red[tid] = fmaxf(red[tid], red[tid + s]);
        __syncthreads();
    }
    m = red[0];
    __syncthreads();

    float sum = 0.0f;
    for (int t = tid; t < T_; t += 256)
        sum += expf(g_logits[b * T_ + t] - m);
    red[tid] = sum;
    __syncthreads();
    for (int s = 128; s > 0; s >>= 1) {
        if (tid < s) red[tid] += red[tid + s];
        __syncthreads();
    }
    const float inv = 1.0f / red[0];

    for (int t = tid; t < T_; t += 256)
        weights[b * T_ + t] = expf(g_logits[b * T_ + t] - m) * inv;
}

// ---------------------------------------------------------------------------
// context: two-stage deterministic reduction over T, float4 loads
// ---------------------------------------------------------------------------
__global__ void context_part_kernel(const float* __restrict__ values,
                                    const float* __restrict__ weights)
{
    __shared__ float w[128];
    const int b = blockIdx.y;
    const int chunk = blockIdx.z;
    const int d4 = blockIdx.x * 64 + threadIdx.x;   // float4 index
    const int tbase = chunk * 128;

    for (int t = threadIdx.x; t < 128; t += 64)
        w[t] = weights[b * T_ + tbase + t];
    __syncthreads();

    const float4* vp4 = (const float4*)(values + ((size_t)b * T_ + tbase) * D_) + d4;
    float4 a0 = {0,0,0,0}, a1 = {0,0,0,0}, a2 = {0,0,0,0}, a3 = {0,0,0,0};
#pragma unroll 2
    for (int t = 0; t < 128; t += 4) {
        float4 f0 = vp4[(size_t)(t + 0) * (D_ / 4)];
        float4 f1 = vp4[(size_t)(t + 1) * (D_ / 4)];
        float4 f2 = vp4[(size_t)(t + 2) * (D_ / 4)];
        float4 f3 = vp4[(size_t)(t + 3) * (D_ / 4)];
        float w0 = w[t], w1 = w[t + 1], w2 = w[t + 2], w3 = w[t + 3];
        a0.x = fmaf(w0, f0.x, a0.x); a0.y = fmaf(w0, f0.y, a0.y);
        a0.z = fmaf(w0, f0.z, a0.z); a0.w = fmaf(w0, f0.w, a0.w);
        a1.x = fmaf(w1, f1.x, a1.x); a1.y = fmaf(w1, f1.y, a1.y);
        a1.z = fmaf(w1, f1.z, a1.z); a1.w = fmaf(w1, f1.w, a1.w);
        a2.x = fmaf(w2, f2.x, a2.x); a2.y = fmaf(w2, f2.y, a2.y);
        a2.z = fmaf(w2, f2.z, a2.z); a2.w = fmaf(w2, f2.w, a2.w);
        a3.x = fmaf(w3, f3.x, a3.x); a3.y = fmaf(w3, f3.y, a3.y);
        a3.z = fmaf(w3, f3.z, a3.z); a3.w = fmaf(w3, f3.w, a3.w);
    }
    float4 r;
    r.x = (a0.x + a1.x) + (a2.x + a3.x);
    r.y = (a0.y + a1.y) + (a2.y + a3.y);
    r.z = (a0.z + a1.z) + (a2.z + a3.z);
    r.w = (a0.w + a1.w) + (a2.w + a3.w);
    ((float4*)(g_cpart + (size_t)(chunk * B_ + b) * D_))[d4] = r;
}

__global__ void context_reduce_kernel(float* __restrict__ context)
{
    const int i = blockIdx.x * 256 + threadIdx.x;   // over B*D
    float s = 0.0f;
#pragma unroll
    for (int c = 0; c < 16; ++c)
        s += g_cpart[c * (B_ * D_) + i];
    context[i] = s;
}

// ---------------------------------------------------------------------------
extern "C" void kernel_launch(void* const* d_in, const int* in_sizes, int n_in,
                              void* d_out, int out_size)
{
    const float* query  = (const float*)d_in[0];
    const float* values = (const float*)d_in[1];
    const float* W1     = (const float*)d_in[2];
    const float* b1     = (const float*)d_in[3];
    const float* W2     = (const float*)d_in[4];
    const float* b2     = (const float*)d_in[5];
    const float* V      = (const float*)d_in[6];
    const float* bv     = (const float*)d_in[7];

    float* out     = (float*)d_out;
    float* context = out;             // [B, D]
    float* weights = out + B_ * D_;   // [B, T, 1]

    cudaFuncSetAttribute(score_kernel,
                         cudaFuncAttributeMaxDynamicSharedMemorySize, SMTOT);

    w1t_kernel<<<dim3(U_ / 32, D_ / 32), dim3(32, 8)>>>(W1);
    qproj_part_kernel<<<dim3(U_ / 256, B_, 8), 256>>>(query, W2);
    qproj_reduce_kernel<<<(B_ * U_) / 256, 256>>>(b1, b2);
    score_kernel<<<(B_ * T_) / 64, 128, SMTOT>>>(values, V, bv);
    softmax_kernel<<<B_, 256>>>(weights);
    context_part_kernel<<<dim3(D_ / 256, B_, 16), 64>>>(values, weights);
    context_reduce_kernel<<<(B_ * D_) / 256, 256>>>(context);
}

// round 12
// speedup vs baseline: 1.8307x; 1.8307x over previous
#include <cuda_runtime.h>
#include <cuda_fp16.h>
#include <math.h>
#include <stdint.h>

#define B_ 32
#define T_ 2048
#define D_ 1024
#define U_ 1024

// ---------------- device scratch (no allocation allowed) ----------------
__device__ float   g_cu[B_ * U_];         // query @ W2 + b2 + b1
__device__ float   g_qpart[8 * B_ * U_];  // qproj split-K partials
__device__ float   g_logits[B_ * T_];     // pre-softmax scores
__device__ __half  g_w1t[U_ * D_];        // W1^T in fp16  [U, D]
__device__ float   g_cpart[16 * B_ * D_]; // context partials

// ---------------- helpers ----------------
__device__ __forceinline__ uint32_t smem_u32(const void* p) {
    uint32_t a;
    asm("{ .reg .u64 t; cvta.to.shared.u64 t, %1; cvt.u32.u64 %0, t; }" : "=r"(a) : "l"(p));
    return a;
}
__device__ __forceinline__ uint32_t pack_f16x2(float lo, float hi) {
    uint32_t r;
    asm("cvt.rn.f16x2.f32 %0, %1, %2;" : "=r"(r) : "f"(hi), "f"(lo));
    return r;
}
__device__ __forceinline__ void ldsm_x4(uint32_t& r0, uint32_t& r1, uint32_t& r2, uint32_t& r3,
                                        uint32_t addr) {
    asm volatile("ldmatrix.sync.aligned.m8n8.x4.shared.b16 {%0,%1,%2,%3}, [%4];"
                 : "=r"(r0), "=r"(r1), "=r"(r2), "=r"(r3) : "r"(addr));
}
__device__ __forceinline__ void mma16816(float* c, const uint32_t* a, uint32_t b0, uint32_t b1) {
    asm volatile(
        "mma.sync.aligned.m16n8k16.row.col.f32.f16.f16.f32 "
        "{%0,%1,%2,%3},{%4,%5,%6,%7},{%8,%9},{%0,%1,%2,%3};"
        : "+f"(c[0]), "+f"(c[1]), "+f"(c[2]), "+f"(c[3])
        : "r"(a[0]), "r"(a[1]), "r"(a[2]), "r"(a[3]), "r"(b0), "r"(b1));
}
__device__ __forceinline__ void cp_async16(uint32_t sdst, const void* gsrc) {
    asm volatile("cp.async.cg.shared.global [%0], [%1], 16;" :: "r"(sdst), "l"(gsrc));
}
__device__ __forceinline__ void cp_commit() {
    asm volatile("cp.async.commit_group;" ::: "memory");
}
__device__ __forceinline__ void cp_wait1() {
    asm volatile("cp.async.wait_group 1;" ::: "memory");
}

// ---------------------------------------------------------------------------
// W1 [D,U] fp32 -> g_w1t [U,D] fp16 (transpose + convert)
// ---------------------------------------------------------------------------
__global__ void w1t_kernel(const float* __restrict__ W1)
{
    __shared__ float tile[32][33];
    const int u0 = blockIdx.x * 32, d0 = blockIdx.y * 32;
    const int tx = threadIdx.x, ty = threadIdx.y;
#pragma unroll
    for (int i = 0; i < 32; i += 8)
        tile[ty + i][tx] = W1[(size_t)(d0 + ty + i) * U_ + u0 + tx];
    __syncthreads();
#pragma unroll
    for (int i = 0; i < 32; i += 8)
        g_w1t[(size_t)(u0 + ty + i) * D_ + d0 + tx] = __float2half_rn(tile[tx][ty + i]);
}

// ---------------------------------------------------------------------------
// q_proj split-K: partial dot over 128 d's per block
// ---------------------------------------------------------------------------
__global__ void qproj_part_kernel(const float* __restrict__ query,
                                  const float* __restrict__ W2)
{
    __shared__ float qs[128];
    const int b = blockIdx.y;
    const int c = blockIdx.z;
    const int u = blockIdx.x * 256 + threadIdx.x;
    const int d0 = c * 128;

    if (threadIdx.x < 128)
        qs[threadIdx.x] = query[b * D_ + d0 + threadIdx.x];
    __syncthreads();

    float acc = 0.0f;
#pragma unroll 8
    for (int i = 0; i < 128; ++i)
        acc = fmaf(qs[i], W2[(size_t)(d0 + i) * U_ + u], acc);
    g_qpart[(c * B_ + b) * U_ + u] = acc;
}

__global__ void qproj_reduce_kernel(const float* __restrict__ b1,
                                    const float* __restrict__ b2)
{
    const int i = blockIdx.x * 256 + threadIdx.x;   // over B*U
    const int u = i & (U_ - 1);
    float s = b1[u] + b2[u];
#pragma unroll
    for (int c = 0; c < 8; ++c)
        s += g_qpart[c * (B_ * U_) + i];
    g_cu[i] = s;
}

// ---------------------------------------------------------------------------
// Fused score GEMM (mma.sync fp16) — warp-private B streaming, NO mainloop
// barriers:
//   logits[b,t] = V . tanh(values[b,t,:] @ W1 + qproj_cu[b,:]) + bv
// 256 threads / 8 warps. Warp tile 64m x 32n: each warp owns a private
// 32-u slice of B, streamed with its OWN cp.async 2-stage ring (chunks of
// 32u x 64k, rows padded to 144B => conflict-free ldsm, no swizzle).
// A (64x1024 fp16) resident & shared (read-only after one initial sync).
// Per chunk: all B-ldsm -> issue next chunk's cp (A never overwritten,
// B stage just consumed) -> per-ks A-ldsm + 16 mma. Warps fully decoupled.
// ---------------------------------------------------------------------------
#define NCHUNK 64                      // 4 passes x 16 chunks of 64k
#define BPITCH 144                     // 128B data + 16B pad (conflict-free)
#define BSTAGE (32 * BPITCH)           // 4608 B per stage
#define SMA    0                       // 64 x 2048B = 131072
#define SMB    131072                  // 8 warps x 2 stages x 4608 = 73728
#define SMRED  (SMB + 8 * 2 * BSTAGE)  // 64 x 8 f32
#define SMTOT  (SMRED + 2048)          // 206848 bytes

__global__ void __launch_bounds__(256, 1)
score_kernel(const float* __restrict__ values,
             const float* __restrict__ V,
             const float* __restrict__ bv)
{
    extern __shared__ char smem[];
    const uint32_t sb = smem_u32(smem);
    const int tid  = threadIdx.x;
    const int lane = tid & 31;
    const int warp = tid >> 5;           // owns u-cols [warp*32, warp*32+32) of each pass
    const int g8 = lane >> 2;
    const int t4 = lane & 3;
    const int e  = lane >> 4;            // 0/1: which 8-col k-group of ldsm

    const int b  = blockIdx.x >> 5;          // 32 t-tiles per batch
    const int t0 = (blockIdx.x & 31) * 64;

    float* sred = (float*)(smem + SMRED);

    // --- per-warp B ring bases ---
    const uint32_t wb = sb + SMB + warp * (2 * BSTAGE);
    // cp.async per-lane constants: slot = lane + j*32 -> row = j*4 + (lane>>3), cs = lane&7
    const uint32_t cp_dst0 = wb + (lane >> 3) * BPITCH + (lane & 7) * 16;
    const char*    cp_src0 = (const char*)g_w1t
                           + ((size_t)warp * 32 + (lane >> 3)) * 2048 + (lane & 7) * 16;

    // chunk issue: 32u x 64k fp16 into this warp's stage gc&1 (8 cp per lane)
    auto issue_chunk = [&](int gc) {
        if (gc < NCHUNK) {
            const uint32_t d0 = cp_dst0 + (uint32_t)(gc & 1) * BSTAGE;
            const char* s0 = cp_src0 + (size_t)(gc >> 4) * 524288 + (gc & 15) * 128;
#pragma unroll
            for (int j = 0; j < 8; ++j)
                cp_async16(d0 + j * (4 * BPITCH), s0 + (size_t)j * 8192);
        }
        cp_commit();
    };

    // prologue: 2 chunks in flight per warp
    issue_chunk(0);
    issue_chunk(1);

    // ---- A resident: 64 rows x 1024 k, fp32 -> fp16, xor-swizzled ----
    const float* vbase = values + ((size_t)b * T_ + t0) * D_;
#pragma unroll 4
    for (int it = 0; it < 32; ++it) {
        int idx = tid + it * 256;             // 8192 slots of 8 fp16
        int row = idx >> 7;
        int c   = idx & 127;
        const float* src = vbase + (size_t)row * D_ + c * 8;
        float4 f0 = *(const float4*)(src);
        float4 f1 = *(const float4*)(src + 4);
        uint4 o;
        o.x = pack_f16x2(f0.x, f0.y);
        o.y = pack_f16x2(f0.z, f0.w);
        o.z = pack_f16x2(f1.x, f1.y);
        o.w = pack_f16x2(f1.z, f1.w);
        *(uint4*)(smem + SMA + row * 2048 + ((c ^ (row & 7)) << 4)) = o;
    }
    __syncthreads();   // the ONLY pre-mainloop block barrier (A visibility)

    // ---- ldsm address bases ----
    const int l15 = lane & 15, swl = lane & 7;
    uint32_t a_base[4];                    // per ks; + mt*32768 + c*128
#pragma unroll
    for (int ks = 0; ks < 4; ++ks)
        a_base[ks] = sb + SMA + l15 * 2048 + (uint32_t)(((2 * ks + e) ^ swl) << 4);
    // B: addr(ks,nt;stage) = wb + stage*BSTAGE + (nt*16+l15)*BPITCH + (2ks+e)*16
    const uint32_t b_base = wb + l15 * BPITCH + e * 16;

    float spart[4][2];
#pragma unroll
    for (int mt = 0; mt < 4; ++mt) { spart[mt][0] = 0.f; spart[mt][1] = 0.f; }

    int g = 0;

    for (int pass = 0; pass < 4; ++pass) {
        const int u0 = pass * 256;

        float acc[4][4][4];     // [mt][j = nt*2+half][frag]
#pragma unroll
        for (int mt = 0; mt < 4; ++mt)
#pragma unroll
            for (int j = 0; j < 4; ++j)
#pragma unroll
                for (int r = 0; r < 4; ++r) acc[mt][j][r] = 0.f;

        for (int c = 0; c < 16; ++c, ++g) {
            cp_wait1();                           // own group: chunk g landed

            const uint32_t bst = b_base + (uint32_t)(g & 1) * BSTAGE;

            // all B fragments for this chunk (stage consumed after this)
            uint32_t bf[4][2][4];                 // [ks][nt][4]
#pragma unroll
            for (int ks = 0; ks < 4; ++ks)
#pragma unroll
                for (int nt = 0; nt < 2; ++nt)
                    ldsm_x4(bf[ks][nt][0], bf[ks][nt][1], bf[ks][nt][2], bf[ks][nt][3],
                            bst + nt * (16 * BPITCH) + ks * 32);

            issue_chunk(g + 2);                   // refill this stage under compute

            const uint32_t a_c = (uint32_t)c * 128;
#pragma unroll
            for (int ks = 0; ks < 4; ++ks) {
                uint32_t af[4][4];
#pragma unroll
                for (int mt = 0; mt < 4; ++mt)
                    ldsm_x4(af[mt][0], af[mt][1], af[mt][2], af[mt][3],
                            a_base[ks] + a_c + mt * 32768);
#pragma unroll
                for (int nt = 0; nt < 2; ++nt)
#pragma unroll
                    for (int mt = 0; mt < 4; ++mt) {
                        mma16816(acc[mt][nt * 2 + 0], af[mt],
                                 bf[ks][nt][0], bf[ks][nt][2]);   // cols +0..7
                        mma16816(acc[mt][nt * 2 + 1], af[mt],
                                 bf[ks][nt][1], bf[ks][nt][3]);   // cols +8..15
                    }
            }
        }

        // ---- epilogue: tanh + dot V folded into per-row partials ----
        float cuv[8], vvv[8];
#pragma unroll
        for (int j = 0; j < 4; ++j)
#pragma unroll
            for (int ee = 0; ee < 2; ++ee) {
                int u = u0 + warp * 32 + j * 8 + t4 * 2 + ee;
                cuv[j * 2 + ee] = g_cu[b * U_ + u];
                vvv[j * 2 + ee] = V[u];
            }
#pragma unroll
        for (int mt = 0; mt < 4; ++mt)
#pragma unroll
            for (int j = 0; j < 4; ++j)
#pragma unroll
                for (int r = 0; r < 4; ++r) {
                    float x = acc[mt][j][r] + cuv[j * 2 + (r & 1)];
                    spart[mt][r >> 1] =
                        fmaf(tanhf(x), vvv[j * 2 + (r & 1)], spart[mt][r >> 1]);
                }
    }

    // reduce across quad lanes (cols), stash per-warp partials
#pragma unroll
    for (int mt = 0; mt < 4; ++mt)
#pragma unroll
        for (int h = 0; h < 2; ++h) {
            float v = spart[mt][h];
            v += __shfl_xor_sync(0xffffffffu, v, 1);
            v += __shfl_xor_sync(0xffffffffu, v, 2);
            if (t4 == 0) {
                int row = mt * 16 + h * 8 + g8;
                sred[row * 8 + warp] = v;
            }
        }
    __syncthreads();
    if (tid < 64) {
        const float* rp = &sred[tid * 8];
        float s = ((rp[0] + rp[1]) + (rp[2] + rp[3]))
                + ((rp[4] + rp[5]) + (rp[6] + rp[7]));
        g_logits[b * T_ + t0 + tid] = s + bv[0];
    }
}

// ---------------------------------------------------------------------------
// softmax over T per batch
// ---------------------------------------------------------------------------
__global__ void softmax_kernel(float* __restrict__ weights)
{
    __shared__ float red[256];
    const int b = blockIdx.x;
    const int tid = threadIdx.x;

    float m = -INFINITY;
    for (int t = tid; t < T_; t += 256)
        m = fmaxf(m, g_logits[b * T_ + t]);
    red[tid] = m;
    __syncthreads();
    for (int s = 128; s > 0; s >>= 1) {
        if (tid < s) red[tid] = fmaxf(red[tid], red[tid + s]);
        __syncthreads();
    }
    m = red[0];
    __syncthreads();

    float sum = 0.0f;
    for (int t = tid; t < T_; t += 256)
        sum += expf(g_logits[b * T_ + t] - m);
    red[tid] = sum;
    __syncthreads();
    for (int s = 128; s > 0; s >>= 1) {
        if (tid < s) red[tid] += red[tid + s];
        __syncthreads();
    }
    const float inv = 1.0f / red[0];

    for (int t = tid; t < T_; t += 256)
        weights[b * T_ + t] = expf(g_logits[b * T_ + t] - m) * inv;
}

// ---------------------------------------------------------------------------
// context: two-stage deterministic reduction over T, float4 loads
// ---------------------------------------------------------------------------
__global__ void context_part_kernel(const float* __restrict__ values,
                                    const float* __restrict__ weights)
{
    __shared__ float w[128];
    const int b = blockIdx.y;
    const int chunk = blockIdx.z;
    const int d4 = blockIdx.x * 64 + threadIdx.x;   // float4 index
    const int tbase = chunk * 128;

    for (int t = threadIdx.x; t < 128; t += 64)
        w[t] = weights[b * T_ + tbase + t];
    __syncthreads();

    const float4* vp4 = (const float4*)(values + ((size_t)b * T_ + tbase) * D_) + d4;
    float4 a0 = {0,0,0,0}, a1 = {0,0,0,0}, a2 = {0,0,0,0}, a3 = {0,0,0,0};
#pragma unroll 2
    for (int t = 0; t < 128; t += 4) {
        float4 f0 = vp4[(size_t)(t + 0) * (D_ / 4)];
        float4 f1 = vp4[(size_t)(t + 1) * (D_ / 4)];
        float4 f2 = vp4[(size_t)(t + 2) * (D_ / 4)];
        float4 f3 = vp4[(size_t)(t + 3) * (D_ / 4)];
        float w0 = w[t], w1 = w[t + 1], w2 = w[t + 2], w3 = w[t + 3];
        a0.x = fmaf(w0, f0.x, a0.x); a0.y = fmaf(w0, f0.y, a0.y);
        a0.z = fmaf(w0, f0.z, a0.z); a0.w = fmaf(w0, f0.w, a0.w);
        a1.x = fmaf(w1, f1.x, a1.x); a1.y = fmaf(w1, f1.y, a1.y);
        a1.z = fmaf(w1, f1.z, a1.z); a1.w = fmaf(w1, f1.w, a1.w);
        a2.x = fmaf(w2, f2.x, a2.x); a2.y = fmaf(w2, f2.y, a2.y);
        a2.z = fmaf(w2, f2.z, a2.z); a2.w = fmaf(w2, f2.w, a2.w);
        a3.x = fmaf(w3, f3.x, a3.x); a3.y = fmaf(w3, f3.y, a3.y);
        a3.z = fmaf(w3, f3.z, a3.z); a3.w = fmaf(w3, f3.w, a3.w);
    }
    float4 r;
    r.x = (a0.x + a1.x) + (a2.x + a3.x);
    r.y = (a0.y + a1.y) + (a2.y + a3.y);
    r.z = (a0.z + a1.z) + (a2.z + a3.z);
    r.w = (a0.w + a1.w) + (a2.w + a3.w);
    ((float4*)(g_cpart + (size_t)(chunk * B_ + b) * D_))[d4] = r;
}

__global__ void context_reduce_kernel(float* __restrict__ context)
{
    const int i = blockIdx.x * 256 + threadIdx.x;   // over B*D
    float s = 0.0f;
#pragma unroll
    for (int c = 0; c < 16; ++c)
        s += g_cpart[c * (B_ * D_) + i];
    context[i] = s;
}

// ---------------------------------------------------------------------------
extern "C" void kernel_launch(void* const* d_in, const int* in_sizes, int n_in,
                              void* d_out, int out_size)
{
    const float* query  = (const float*)d_in[0];
    const float* values = (const float*)d_in[1];
    const float* W1     = (const float*)d_in[2];
    const float* b1     = (const float*)d_in[3];
    const float* W2     = (const float*)d_in[4];
    const float* b2     = (const float*)d_in[5];
    const float* V      = (const float*)d_in[6];
    const float* bv     = (const float*)d_in[7];

    float* out     = (float*)d_out;
    float* context = out;             // [B, D]
    float* weights = out + B_ * D_;   // [B, T, 1]

    cudaFuncSetAttribute(score_kernel,
                         cudaFuncAttributeMaxDynamicSharedMemorySize, SMTOT);

    w1t_kernel<<<dim3(U_ / 32, D_ / 32), dim3(32, 8)>>>(W1);
    qproj_part_kernel<<<dim3(U_ / 256, B_, 8), 256>>>(query, W2);
    qproj_reduce_kernel<<<(B_ * U_) / 256, 256>>>(b1, b2);
    score_kernel<<<(B_ * T_) / 64, 256, SMTOT>>>(values, V, bv);
    softmax_kernel<<<B_, 256>>>(weights);
    context_part_kernel<<<dim3(D_ / 256, B_, 16), 64>>>(values, weights);
    context_reduce_kernel<<<(B_ * D_) / 256, 256>>>(context);
}

// round 13
// speedup vs baseline: 1.9015x; 1.0387x over previous
#include <cuda_runtime.h>
#include <cuda_fp16.h>
#include <math.h>
#include <stdint.h>

#define B_ 32
#define T_ 2048
#define D_ 1024
#define U_ 1024

// ---------------- device scratch (no allocation allowed) ----------------
__device__ float   g_cu[B_ * U_];         // query @ W2 + b2 + b1
__device__ float   g_qpart[8 * B_ * U_];  // qproj split-K partials
__device__ float   g_logits[B_ * T_];     // pre-softmax scores
__device__ __half  g_w1t[U_ * D_];        // W1^T in fp16  [U, D]
__device__ float   g_cpart[16 * B_ * D_]; // context partials

// ---------------- helpers ----------------
__device__ __forceinline__ uint32_t smem_u32(const void* p) {
    uint32_t a;
    asm("{ .reg .u64 t; cvta.to.shared.u64 t, %1; cvt.u32.u64 %0, t; }" : "=r"(a) : "l"(p));
    return a;
}
__device__ __forceinline__ uint32_t pack_f16x2(float lo, float hi) {
    uint32_t r;
    asm("cvt.rn.f16x2.f32 %0, %1, %2;" : "=r"(r) : "f"(hi), "f"(lo));
    return r;
}
__device__ __forceinline__ void ldsm_x4(uint32_t& r0, uint32_t& r1, uint32_t& r2, uint32_t& r3,
                                        uint32_t addr) {
    asm volatile("ldmatrix.sync.aligned.m8n8.x4.shared.b16 {%0,%1,%2,%3}, [%4];"
                 : "=r"(r0), "=r"(r1), "=r"(r2), "=r"(r3) : "r"(addr));
}
__device__ __forceinline__ void mma16816(float* c, const uint32_t* a, uint32_t b0, uint32_t b1) {
    asm volatile(
        "mma.sync.aligned.m16n8k16.row.col.f32.f16.f16.f32 "
        "{%0,%1,%2,%3},{%4,%5,%6,%7},{%8,%9},{%0,%1,%2,%3};"
        : "+f"(c[0]), "+f"(c[1]), "+f"(c[2]), "+f"(c[3])
        : "r"(a[0]), "r"(a[1]), "r"(a[2]), "r"(a[3]), "r"(b0), "r"(b1));
}
__device__ __forceinline__ void cp_async16(uint32_t sdst, const void* gsrc) {
    asm volatile("cp.async.cg.shared.global [%0], [%1], 16;" :: "r"(sdst), "l"(gsrc));
}
__device__ __forceinline__ void cp_commit() {
    asm volatile("cp.async.commit_group;" ::: "memory");
}
__device__ __forceinline__ void cp_wait1() {
    asm volatile("cp.async.wait_group 1;" ::: "memory");
}

// ---------------------------------------------------------------------------
// W1 [D,U] fp32 -> g_w1t [U,D] fp16 (transpose + convert)
// ---------------------------------------------------------------------------
__global__ void w1t_kernel(const float* __restrict__ W1)
{
    __shared__ float tile[32][33];
    const int u0 = blockIdx.x * 32, d0 = blockIdx.y * 32;
    const int tx = threadIdx.x, ty = threadIdx.y;
#pragma unroll
    for (int i = 0; i < 32; i += 8)
        tile[ty + i][tx] = W1[(size_t)(d0 + ty + i) * U_ + u0 + tx];
    __syncthreads();
#pragma unroll
    for (int i = 0; i < 32; i += 8)
        g_w1t[(size_t)(u0 + ty + i) * D_ + d0 + tx] = __float2half_rn(tile[tx][ty + i]);
}

// ---------------------------------------------------------------------------
// q_proj split-K: partial dot over 128 d's per block
// ---------------------------------------------------------------------------
__global__ void qproj_part_kernel(const float* __restrict__ query,
                                  const float* __restrict__ W2)
{
    __shared__ float qs[128];
    const int b = blockIdx.y;
    const int c = blockIdx.z;
    const int u = blockIdx.x * 256 + threadIdx.x;
    const int d0 = c * 128;

    if (threadIdx.x < 128)
        qs[threadIdx.x] = query[b * D_ + d0 + threadIdx.x];
    __syncthreads();

    float acc = 0.0f;
#pragma unroll 8
    for (int i = 0; i < 128; ++i)
        acc = fmaf(qs[i], W2[(size_t)(d0 + i) * U_ + u], acc);
    g_qpart[(c * B_ + b) * U_ + u] = acc;
}

__global__ void qproj_reduce_kernel(const float* __restrict__ b1,
                                    const float* __restrict__ b2)
{
    const int i = blockIdx.x * 256 + threadIdx.x;   // over B*U
    const int u = i & (U_ - 1);
    float s = b1[u] + b2[u];
#pragma unroll
    for (int c = 0; c < 8; ++c)
        s += g_qpart[c * (B_ * U_) + i];
    g_cu[i] = s;
}

// ---------------------------------------------------------------------------
// Fused score GEMM (mma.sync fp16) — 16 decoupled warp streams, no mainloop
// barriers:
//   logits[b,t] = V . tanh(values[b,t,:] @ W1 + qproj_cu[b,:]) + bv
// 512 threads / 16 warps, 4 per SMSP. Warp tile 64m x 32n: each warp owns a
// private 32-u slice per pass, streamed with its OWN 2-stage cp.async ring
// (chunks of 32u x 32k, rows padded to 80B => conflict-free ldsm, no
// swizzle). A (64x1024 fp16) resident & shared (read-only after one initial
// sync). 2 passes x 32 chunks. Per chunk: all B-ldsm -> issue next chunk's
// cp -> per-ks A-ldsm + 16 mma. Warps fully decoupled.
// ---------------------------------------------------------------------------
#define NCHUNK 64                      // 2 passes x 32 chunks of 32k
#define BPITCH 80                      // 64B data + 16B pad (conflict-free)
#define BSTAGE (32 * BPITCH)           // 2560 B per stage
#define SMA    0                       // 64 x 2048B = 131072
#define SMB    131072                  // 16 warps x 2 stages x 2560 = 81920
#define SMRED  (SMB + 16 * 2 * BSTAGE) // 64 x 16 f32
#define SMTOT  (SMRED + 4096)          // 217088 bytes

__global__ void __launch_bounds__(512, 1)
score_kernel(const float* __restrict__ values,
             const float* __restrict__ V,
             const float* __restrict__ bv)
{
    extern __shared__ char smem[];
    const uint32_t sb = smem_u32(smem);
    const int tid  = threadIdx.x;
    const int lane = tid & 31;
    const int warp = tid >> 5;           // owns u-cols [p*512 + warp*32, +32)
    const int g8 = lane >> 2;
    const int t4 = lane & 3;
    const int e  = lane >> 4;            // 0/1: which 8-col k-group of ldsm

    const int b  = blockIdx.x >> 5;          // 32 t-tiles per batch
    const int t0 = (blockIdx.x & 31) * 64;

    float* sred = (float*)(smem + SMRED);

    // --- per-warp B ring bases ---
    const uint32_t wb = sb + SMB + warp * (2 * BSTAGE);
    // cp.async: slot = j*32 + lane -> row = j*8 + (lane>>2), col16 = lane&3
    const uint32_t cp_dst0 = wb + (lane >> 2) * BPITCH + (lane & 3) * 16;
    const char*    cp_src0 = (const char*)g_w1t
                           + ((size_t)warp * 32 + (lane >> 2)) * 2048 + (lane & 3) * 16;

    // chunk issue: 32u x 32k fp16 into this warp's stage gc&1 (4 cp per lane)
    auto issue_chunk = [&](int gc) {
        if (gc < NCHUNK) {
            const uint32_t d0 = cp_dst0 + (uint32_t)(gc & 1) * BSTAGE;
            const char* s0 = cp_src0 + (size_t)(gc >> 5) * 1048576 + (gc & 31) * 64;
#pragma unroll
            for (int j = 0; j < 4; ++j)
                cp_async16(d0 + j * (8 * BPITCH), s0 + (size_t)j * 16384);
        }
        cp_commit();
    };

    // prologue: 2 chunks in flight per warp
    issue_chunk(0);
    issue_chunk(1);

    // ---- A resident: 64 rows x 1024 k, fp32 -> fp16, xor-swizzled ----
    const float* vbase = values + ((size_t)b * T_ + t0) * D_;
#pragma unroll 4
    for (int it = 0; it < 16; ++it) {
        int idx = tid + it * 512;             // 8192 slots of 8 fp16
        int row = idx >> 7;
        int c   = idx & 127;
        const float* src = vbase + (size_t)row * D_ + c * 8;
        float4 f0 = *(const float4*)(src);
        float4 f1 = *(const float4*)(src + 4);
        uint4 o;
        o.x = pack_f16x2(f0.x, f0.y);
        o.y = pack_f16x2(f0.z, f0.w);
        o.z = pack_f16x2(f1.x, f1.y);
        o.w = pack_f16x2(f1.z, f1.w);
        *(uint4*)(smem + SMA + row * 2048 + ((c ^ (row & 7)) << 4)) = o;
    }
    __syncthreads();   // the ONLY pre-mainloop block barrier (A visibility)

    // ---- ldsm address bases ----
    const int l15 = lane & 15, swl = lane & 7;
    // A 16B-slot index: cc = c*4 + 2ks + e; swizzle XORs low 3 bits (row&7).
    // Split: a_sw[c&1][ks] = (((c&1)*4 + 2ks + e) ^ swl) << 4 ; + (c>>1)*128.
    const uint32_t aRow = sb + SMA + l15 * 2048;
    uint32_t a_sw[2][2];
#pragma unroll
    for (int q = 0; q < 2; ++q)
#pragma unroll
        for (int ks = 0; ks < 2; ++ks)
            a_sw[q][ks] = (uint32_t)(((q * 4 + 2 * ks + e) ^ swl) << 4);
    // B: addr(ks,nt;stage) = wb + stage*BSTAGE + (nt*16+l15)*BPITCH + e*16 + ks*32
    const uint32_t b_base = wb + l15 * BPITCH + e * 16;

    float spart[4][2];
#pragma unroll
    for (int mt = 0; mt < 4; ++mt) { spart[mt][0] = 0.f; spart[mt][1] = 0.f; }

    int g = 0;

    for (int pass = 0; pass < 2; ++pass) {
        const int u0 = pass * 512;

        float acc[4][4][4];     // [mt][j = nt*2+half][frag]
#pragma unroll
        for (int mt = 0; mt < 4; ++mt)
#pragma unroll
            for (int j = 0; j < 4; ++j)
#pragma unroll
                for (int r = 0; r < 4; ++r) acc[mt][j][r] = 0.f;

        for (int c = 0; c < 32; ++c, ++g) {
            cp_wait1();                           // own group: chunk g landed

            const uint32_t bst = b_base + (uint32_t)(g & 1) * BSTAGE;

            // all B fragments for this chunk (stage consumed after this)
            uint32_t bf[2][2][4];                 // [ks][nt][4]
#pragma unroll
            for (int ks = 0; ks < 2; ++ks)
#pragma unroll
                for (int nt = 0; nt < 2; ++nt)
                    ldsm_x4(bf[ks][nt][0], bf[ks][nt][1], bf[ks][nt][2], bf[ks][nt][3],
                            bst + nt * (16 * BPITCH) + ks * 32);

            issue_chunk(g + 2);                   // refill this stage under compute

            const uint32_t a_c = aRow + (uint32_t)(c >> 1) * 128;
            const int q = c & 1;
#pragma unroll
            for (int ks = 0; ks < 2; ++ks) {
                uint32_t af[4][4];
#pragma unroll
                for (int mt = 0; mt < 4; ++mt)
                    ldsm_x4(af[mt][0], af[mt][1], af[mt][2], af[mt][3],
                            a_c + a_sw[q][ks] + mt * 32768);
#pragma unroll
                for (int nt = 0; nt < 2; ++nt)
#pragma unroll
                    for (int mt = 0; mt < 4; ++mt) {
                        mma16816(acc[mt][nt * 2 + 0], af[mt],
                                 bf[ks][nt][0], bf[ks][nt][2]);   // cols +0..7
                        mma16816(acc[mt][nt * 2 + 1], af[mt],
                                 bf[ks][nt][1], bf[ks][nt][3]);   // cols +8..15
                    }
            }
        }

        // ---- epilogue: tanh + dot V folded into per-row partials ----
        float cuv[8], vvv[8];
#pragma unroll
        for (int j = 0; j < 4; ++j)
#pragma unroll
            for (int ee = 0; ee < 2; ++ee) {
                int u = u0 + warp * 32 + j * 8 + t4 * 2 + ee;
                cuv[j * 2 + ee] = g_cu[b * U_ + u];
                vvv[j * 2 + ee] = V[u];
            }
#pragma unroll
        for (int mt = 0; mt < 4; ++mt)
#pragma unroll
            for (int j = 0; j < 4; ++j)
#pragma unroll
                for (int r = 0; r < 4; ++r) {
                    float x = acc[mt][j][r] + cuv[j * 2 + (r & 1)];
                    spart[mt][r >> 1] =
                        fmaf(tanhf(x), vvv[j * 2 + (r & 1)], spart[mt][r >> 1]);
                }
    }

    // reduce across quad lanes (cols), stash per-warp partials
#pragma unroll
    for (int mt = 0; mt < 4; ++mt)
#pragma unroll
        for (int h = 0; h < 2; ++h) {
            float v = spart[mt][h];
            v += __shfl_xor_sync(0xffffffffu, v, 1);
            v += __shfl_xor_sync(0xffffffffu, v, 2);
            if (t4 == 0) {
                int row = mt * 16 + h * 8 + g8;
                sred[row * 16 + warp] = v;
            }
        }
    __syncthreads();
    if (tid < 64) {
        const float* rp = &sred[tid * 16];
        float s = 0.0f;
#pragma unroll
        for (int w = 0; w < 16; ++w) s += rp[w];
        g_logits[b * T_ + t0 + tid] = s + bv[0];
    }
}

// ---------------------------------------------------------------------------
// softmax over T per batch
// ---------------------------------------------------------------------------
__global__ void softmax_kernel(float* __restrict__ weights)
{
    __shared__ float red[256];
    const int b = blockIdx.x;
    const int tid = threadIdx.x;

    float m = -INFINITY;
    for (int t = tid; t < T_; t += 256)
        m = fmaxf(m, g_logits[b * T_ + t]);
    red[tid] = m;
    __syncthreads();
    for (int s = 128; s > 0; s >>= 1) {
        if (tid < s) red[tid] = fmaxf(red[tid], red[tid + s]);
        __syncthreads();
    }
    m = red[0];
    __syncthreads();

    float sum = 0.0f;
    for (int t = tid; t < T_; t += 256)
        sum += expf(g_logits[b * T_ + t] - m);
    red[tid] = sum;
    __syncthreads();
    for (int s = 128; s > 0; s >>= 1) {
        if (tid < s) red[tid] += red[tid + s];
        __syncthreads();
    }
    const float inv = 1.0f / red[0];

    for (int t = tid; t < T_; t += 256)
        weights[b * T_ + t] = expf(g_logits[b * T_ + t] - m) * inv;
}

// ---------------------------------------------------------------------------
// context: two-stage deterministic reduction over T, float4 loads
// ---------------------------------------------------------------------------
__global__ void context_part_kernel(const float* __restrict__ values,
                                    const float* __restrict__ weights)
{
    __shared__ float w[128];
    const int b = blockIdx.y;
    const int chunk = blockIdx.z;
    const int d4 = blockIdx.x * 64 + threadIdx.x;   // float4 index
    const int tbase = chunk * 128;

    for (int t = threadIdx.x; t < 128; t += 64)
        w[t] = weights[b * T_ + tbase + t];
    __syncthreads();

    const float4* vp4 = (const float4*)(values + ((size_t)b * T_ + tbase) * D_) + d4;
    float4 a0 = {0,0,0,0}, a1 = {0,0,0,0}, a2 = {0,0,0,0}, a3 = {0,0,0,0};
#pragma unroll 2
    for (int t = 0; t < 128; t += 4) {
        float4 f0 = vp4[(size_t)(t + 0) * (D_ / 4)];
        float4 f1 = vp4[(size_t)(t + 1) * (D_ / 4)];
        float4 f2 = vp4[(size_t)(t + 2) * (D_ / 4)];
        float4 f3 = vp4[(size_t)(t + 3) * (D_ / 4)];
        float w0 = w[t], w1 = w[t + 1], w2 = w[t + 2], w3 = w[t + 3];
        a0.x = fmaf(w0, f0.x, a0.x); a0.y = fmaf(w0, f0.y, a0.y);
        a0.z = fmaf(w0, f0.z, a0.z); a0.w = fmaf(w0, f0.w, a0.w);
        a1.x = fmaf(w1, f1.x, a1.x); a1.y = fmaf(w1, f1.y, a1.y);
        a1.z = fmaf(w1, f1.z, a1.z); a1.w = fmaf(w1, f1.w, a1.w);
        a2.x = fmaf(w2, f2.x, a2.x); a2.y = fmaf(w2, f2.y, a2.y);
        a2.z = fmaf(w2, f2.z, a2.z); a2.w = fmaf(w2, f2.w, a2.w);
        a3.x = fmaf(w3, f3.x, a3.x); a3.y = fmaf(w3, f3.y, a3.y);
        a3.z = fmaf(w3, f3.z, a3.z); a3.w = fmaf(w3, f3.w, a3.w);
    }
    float4 r;
    r.x = (a0.x + a1.x) + (a2.x + a3.x);
    r.y = (a0.y + a1.y) + (a2.y + a3.y);
    r.z = (a0.z + a1.z) + (a2.z + a3.z);
    r.w = (a0.w + a1.w) + (a2.w + a3.w);
    ((float4*)(g_cpart + (size_t)(chunk * B_ + b) * D_))[d4] = r;
}

__global__ void context_reduce_kernel(float* __restrict__ context)
{
    const int i = blockIdx.x * 256 + threadIdx.x;   // over B*D
    float s = 0.0f;
#pragma unroll
    for (int c = 0; c < 16; ++c)
        s += g_cpart[c * (B_ * D_) + i];
    context[i] = s;
}

// ---------------------------------------------------------------------------
extern "C" void kernel_launch(void* const* d_in, const int* in_sizes, int n_in,
                              void* d_out, int out_size)
{
    const float* query  = (const float*)d_in[0];
    const float* values = (const float*)d_in[1];
    const float* W1     = (const float*)d_in[2];
    const float* b1     = (const float*)d_in[3];
    const float* W2     = (const float*)d_in[4];
    const float* b2     = (const float*)d_in[5];
    const float* V      = (const float*)d_in[6];
    const float* bv     = (const float*)d_in[7];

    float* out     = (float*)d_out;
    float* context = out;             // [B, D]
    float* weights = out + B_ * D_;   // [B, T, 1]

    cudaFuncSetAttribute(score_kernel,
                         cudaFuncAttributeMaxDynamicSharedMemorySize, SMTOT);

    w1t_kernel<<<dim3(U_ / 32, D_ / 32), dim3(32, 8)>>>(W1);
    qproj_part_kernel<<<dim3(U_ / 256, B_, 8), 256>>>(query, W2);
    qproj_reduce_kernel<<<(B_ * U_) / 256, 256>>>(b1, b2);
    score_kernel<<<(B_ * T_) / 64, 512, SMTOT>>>(values, V, bv);
    softmax_kernel<<<B_, 256>>>(weights);
    context_part_kernel<<<dim3(D_ / 256, B_, 16), 64>>>(values, weights);
    context_reduce_kernel<<<(B_ * D_) / 256, 256>>>(context);
}